// round 8
// baseline (speedup 1.0000x reference)
#include <cuda_runtime.h>
#include <cuda_bf16.h>
#include <math.h>
#include <stdint.h>

// ---------------------------------------------------------------------------
// VQ-VAE forward — bf16x6 / bf16x3 mma.sync GEMM, ldmatrix fragment loads.
// B=32, CIN=3, IMG=128, D=256, K=512. Latent 32x32.
// ---------------------------------------------------------------------------

#define N_LAT 32768      // B * 32 * 32
#define N_HALF 131072    // B * 64 * 64
#define WPLANE 5242880   // weight plane stride (elements)

// ---- scratch (device globals; allocation is forbidden) ----
static __device__ __nv_bfloat16 g_colh[402653184]; // 3 planes x 134217728 (max N*K_pad)
static __device__ __nv_bfloat16 g_wtsh[15728640];  // 3 planes x 5242880
static __device__ float g_h1[33554432];    // (32,256,64,64)
static __device__ float g_h2[8388608];     // (32,256,32,32)
static __device__ float g_t[8388608];
static __device__ float g_a[8388608];
static __device__ float g_ze[8388608];
static __device__ float g_zq[8388608];
static __device__ float g_b2[8388608];
static __device__ float g_s[16777216];     // (512, 32768) VQ scores
static __device__ float g_d1[33554432];    // (32,256,64,64) deconv1 out
static __device__ int   g_idx[32768];
static __device__ float g_enorm[512];
static __device__ float g_wpk[12288];      // deconv2 repacked weights (fp32)
static __device__ float g_part[1024];      // loss partials

// weight offsets within one plane (elements)
#define OFF_C1    0          // 256 x 64
#define OFF_C2    16384      // 256 x 4096
#define OFF_ER1A  1064960    // 256 x 2304
#define OFF_ER1B  1654784    // 256 x 256
#define OFF_ER2A  1720320
#define OFF_ER2B  2310144
#define OFF_DR1A  2375680
#define OFF_DR1B  2965504
#define OFF_DR2A  3031040
#define OFF_DR2B  3620864
#define OFF_EMB   3686400    // 512 x 256
#define OFF_DT1   3817472    // 4 x (256 x 1024)

// ---------------------------------------------------------------------------
// helpers
// ---------------------------------------------------------------------------
__device__ __forceinline__ uint32_t smem_u32(const void* p) {
    uint32_t a;
    asm("{ .reg .u64 t; cvta.to.shared.u64 t, %1; cvt.u32.u64 %0, t; }" : "=r"(a) : "l"(p));
    return a;
}

__device__ __forceinline__ void cp16(uint32_t dst, const void* src) {
    asm volatile("cp.async.cg.shared.global [%0], [%1], 16;" :: "r"(dst), "l"(src));
}

__device__ __forceinline__ void ldm_x4(uint32_t* r, uint32_t a) {
    asm volatile("ldmatrix.sync.aligned.m8n8.x4.shared.b16 {%0,%1,%2,%3}, [%4];"
        : "=r"(r[0]), "=r"(r[1]), "=r"(r[2]), "=r"(r[3]) : "r"(a));
}

__device__ __forceinline__ void mma16(float* d, const uint32_t* a, const uint32_t* b) {
    asm volatile(
        "mma.sync.aligned.m16n8k16.row.col.f32.bf16.bf16.f32 "
        "{%0,%1,%2,%3}, {%4,%5,%6,%7}, {%8,%9}, {%0,%1,%2,%3};"
        : "+f"(d[0]), "+f"(d[1]), "+f"(d[2]), "+f"(d[3])
        : "r"(a[0]), "r"(a[1]), "r"(a[2]), "r"(a[3]), "r"(b[0]), "r"(b[1]));
}

// exact 3-way bf16 split: v = b0 + b1 + b2 (+ O(2^-27 v))
__device__ __forceinline__ void split3(float v, uint16_t& q0, uint16_t& q1, uint16_t& q2) {
    __nv_bfloat16 h0 = __float2bfloat16(v);
    float r1 = v - __bfloat162float(h0);
    __nv_bfloat16 h1 = __float2bfloat16(r1);
    float r2 = r1 - __bfloat162float(h1);
    __nv_bfloat16 h2 = __float2bfloat16(r2);
    q0 = __bfloat16_as_ushort(h0);
    q1 = __bfloat16_as_ushort(h1);
    q2 = __bfloat16_as_ushort(h2);
}

__device__ __forceinline__ uint32_t pack2(uint16_t lo, uint16_t hi) {
    return (uint32_t)lo | ((uint32_t)hi << 16);
}

// ---------------------------------------------------------------------------
// bf16x GEMM:  C[m][n] = sum_k A[m][k] * Bc[n][k]
//   A3/B3: 3 bf16 planes [M][K_pad] / [N][K_pad], plane strides aStride/bStride.
//   full=1: 6 products (fp32-grade); full=0: 3 products (~1e-5).
//   CTA 128(M) x 128(N), 8 warps (warp 64x32), k-step 32, 3-stage cp.async.
//   Smem rows: 80B stride (64B data + 16B pad) -> ldmatrix conflict-free.
//   Epilogue: conv-style NCHW scatter with bias/resid/relu.
// ---------------------------------------------------------------------------
#define GEMM_SMEM_H 184320   // 3 stages * 6 planes * 128 rows * 80 B

__global__ void __launch_bounds__(256, 1) gemm_bf16x(
    const __nv_bfloat16* __restrict__ A3, size_t aStride,
    const __nv_bfloat16* __restrict__ B3, size_t bStride,
    float* __restrict__ C, int M, int K_pad, int full,
    int logHW, int logW, int Hout, int Wout,
    int sy, int sx, int ry, int rx,
    const float* __restrict__ bias, const float* __restrict__ resid, int relu)
{
    extern __shared__ char smc[];
    const int tid = threadIdx.x;
    const int lane = tid & 31, warp = tid >> 5;
    const int g = lane >> 2, t = lane & 3;
    const int wm = (warp >> 2) << 6;   // 0/64
    const int wn = (warp & 3) << 5;    // 0..96
    const int bm = blockIdx.x << 7;    // m-tile fastest -> B reuse in L2
    const int bn = blockIdx.y << 7;
    const uint32_t sb = smem_u32(smc);
    const int nk = K_pad >> 5;
    const uint32_t lrow = lane & 15;
    const uint32_t lk = (lane >> 4) << 4;

    float acc[4][4][4];
#pragma unroll
    for (int i = 0; i < 4; i++)
#pragma unroll
        for (int j = 0; j < 4; j++)
#pragma unroll
            for (int q = 0; q < 4; q++) acc[i][j][q] = 0.f;

    // stage layout: A planes 0..2 at p*10240, B planes at 30720 + p*10240
    auto loadStage = [&](int it, int slot) {
        const int k0 = it << 5;
        const uint32_t st = sb + slot * 61440;
#pragma unroll
        for (int j = 0; j < 12; j++) {
            int c = j * 256 + tid;
            int pg = c >> 9;              // 0..5 (uniform per j)
            int r  = (c >> 2) & 127;
            int u  = c & 3;
            const __nv_bfloat16* src;
            if (pg < 3) src = A3 + (size_t)pg * aStride + (size_t)(bm + r) * K_pad + k0 + u * 8;
            else        src = B3 + (size_t)(pg - 3) * bStride + (size_t)(bn + r) * K_pad + k0 + u * 8;
            cp16(st + pg * 10240 + r * 80 + u * 16, src);
        }
        asm volatile("cp.async.commit_group;");
    };

    loadStage(0, 0);
    if (nk > 1) loadStage(1, 1);

    for (int it = 0; it < nk; it++) {
        if (it <= nk - 2) asm volatile("cp.async.wait_group 1;");
        else              asm volatile("cp.async.wait_group 0;");
        __syncthreads();
        if (it + 2 < nk) loadStage(it + 2, (it + 2) % 3);

        const uint32_t st = sb + (it % 3) * 61440;
#pragma unroll
        for (int h = 0; h < 2; h++) {
            uint32_t af[4][3][4];
            uint32_t bf[4][3][2];
            // ---- A fragments via ldmatrix.x4: planes 0,1 (+2 if full) ----
#pragma unroll
            for (int mt = 0; mt < 4; mt++) {
                uint32_t rbase = st + (wm + (mt << 4) + lrow) * 80 + (h << 5) + lk;
                ldm_x4(af[mt][0], rbase);
                ldm_x4(af[mt][1], rbase + 10240);
                if (full) ldm_x4(af[mt][2], rbase + 20480);
            }
            // ---- B fragments via ldmatrix.x4 over nt pairs ----
#pragma unroll
            for (int np = 0; np < 2; np++) {
                uint32_t rbase = st + 30720 + (wn + (np << 4) + lrow) * 80 + (h << 5) + lk;
#pragma unroll
                for (int p = 0; p < 3; p++) {
                    if (p == 2 && !full) break;
                    uint32_t r[4];
                    ldm_x4(r, rbase + p * 10240);
                    bf[np * 2 + 0][p][0] = r[0];
                    bf[np * 2 + 1][p][0] = r[1];
                    bf[np * 2 + 0][p][1] = r[2];
                    bf[np * 2 + 1][p][1] = r[3];
                }
            }
            // ---- products, 16 independent chains per product ----
#pragma unroll
            for (int mt = 0; mt < 4; mt++)
#pragma unroll
                for (int nt = 0; nt < 4; nt++) mma16(acc[mt][nt], af[mt][0], bf[nt][0]);
#pragma unroll
            for (int mt = 0; mt < 4; mt++)
#pragma unroll
                for (int nt = 0; nt < 4; nt++) mma16(acc[mt][nt], af[mt][1], bf[nt][0]);
#pragma unroll
            for (int mt = 0; mt < 4; mt++)
#pragma unroll
                for (int nt = 0; nt < 4; nt++) mma16(acc[mt][nt], af[mt][0], bf[nt][1]);
            if (full) {
#pragma unroll
                for (int mt = 0; mt < 4; mt++)
#pragma unroll
                    for (int nt = 0; nt < 4; nt++) mma16(acc[mt][nt], af[mt][1], bf[nt][1]);
#pragma unroll
                for (int mt = 0; mt < 4; mt++)
#pragma unroll
                    for (int nt = 0; nt < 4; nt++) mma16(acc[mt][nt], af[mt][2], bf[nt][0]);
#pragma unroll
                for (int mt = 0; mt < 4; mt++)
#pragma unroll
                    for (int nt = 0; nt < 4; nt++) mma16(acc[mt][nt], af[mt][0], bf[nt][2]);
            }
        }
    }

    // ---- epilogue: NCHW conv scatter ----
    const int HWout = Hout * Wout;
    const int hwmask = (1 << logHW) - 1;
    const int wmask = (1 << logW) - 1;
#pragma unroll
    for (int mt = 0; mt < 4; mt++) {
#pragma unroll
        for (int half = 0; half < 2; half++) {
            int m = bm + wm + (mt << 4) + g + (half << 3);
            float bv = bias ? bias[m] : 0.f;
            int mb = m * HWout;
#pragma unroll
            for (int nt = 0; nt < 4; nt++) {
                int n = bn + wn + (nt << 3) + (t << 1);
                int bimg = n >> logHW;
                int p = n & hwmask;
                int yy = p >> logW, xx = p & wmask;
                int o = bimg * M * HWout + mb + (yy * sy + ry) * Wout + xx * sx + rx;
                float v0 = acc[mt][nt][half * 2 + 0] + bv;
                float v1 = acc[mt][nt][half * 2 + 1] + bv;
                if (resid) { v0 += resid[o]; v1 += resid[o + sx]; }
                if (relu) { v0 = fmaxf(v0, 0.f); v1 = fmaxf(v1, 0.f); }
                C[o] = v0;
                C[o + sx] = v1;
            }
        }
    }
}

// ---------------------------------------------------------------------------
// im2colT: build 3 bf16 planes of colT[N][K_pad], 32x32 smem-staged transpose.
// ---------------------------------------------------------------------------
__global__ void im2colT_conv_h(const float* __restrict__ in, __nv_bfloat16* __restrict__ colh,
                               size_t planeStride,
                               int C, int Hin, int Win, int logHW, int logW,
                               int RS, int S, int stride, int pad, int K, int K_pad)
{
    __shared__ float s[32][33];
    const int tid = threadIdx.x;
    const int n0 = blockIdx.x << 5, k0 = blockIdx.y << 5;
    const int nl = tid & 31, kr = tid >> 5;
    const int n = n0 + nl;
    const int b = n >> logHW;
    const int p = n & ((1 << logHW) - 1);
    const int oy = p >> logW, ox = p & ((1 << logW) - 1);
#pragma unroll
    for (int pass = 0; pass < 4; pass++) {
        int k = k0 + pass * 8 + kr;
        float v = 0.f;
        if (k < K) {
            int ci = k / RS;
            int rs = k - ci * RS;
            int r = rs / S, ss = rs - r * S;
            int iy = oy * stride - pad + r;
            int ix = ox * stride - pad + ss;
            if ((unsigned)iy < (unsigned)Hin && (unsigned)ix < (unsigned)Win)
                v = in[((b * C + ci) * Hin + iy) * Win + ix];
        }
        s[pass * 8 + kr][nl] = v;
    }
    __syncthreads();
    const int onl = tid >> 3, kq = tid & 7;
    uint16_t q0[4], q1[4], q2[4];
#pragma unroll
    for (int j = 0; j < 4; j++) split3(s[kq * 4 + j][onl], q0[j], q1[j], q2[j]);
    size_t base = (size_t)(n0 + onl) * K_pad + k0 + kq * 4;
    *(uint2*)(colh + base)                   = make_uint2(pack2(q0[0], q0[1]), pack2(q0[2], q0[3]));
    *(uint2*)(colh + planeStride + base)     = make_uint2(pack2(q1[0], q1[1]), pack2(q1[2], q1[3]));
    *(uint2*)(colh + 2 * planeStride + base) = make_uint2(pack2(q2[0], q2[1]), pack2(q2[2], q2[3]));
}

// im2colT for transposed-conv parity class (ry,rx): k = ci*4 + a*2 + bb
__global__ void im2colT_dec_h(const float* __restrict__ in, __nv_bfloat16* __restrict__ colh,
                              size_t planeStride, int ry, int rx)
{
    __shared__ float s[32][33];
    const int tid = threadIdx.x;
    const int n0 = blockIdx.x << 5, k0 = blockIdx.y << 5;
    const int nl = tid & 31, kr = tid >> 5;
    const int n = n0 + nl;
    const int b = n >> 10;
    const int p = n & 1023;
    const int my = p >> 5, mx = p & 31;
#pragma unroll
    for (int pass = 0; pass < 4; pass++) {
        int k = k0 + pass * 8 + kr;
        int ci = k >> 2;
        int a = (k >> 1) & 1, bb = k & 1;
        int iy = my + a - 1 + ry, ix = mx + bb - 1 + rx;
        float v = 0.f;
        if ((unsigned)iy < 32u && (unsigned)ix < 32u)
            v = in[((b * 256 + ci) * 32 + iy) * 32 + ix];
        s[pass * 8 + kr][nl] = v;
    }
    __syncthreads();
    const int onl = tid >> 3, kq = tid & 7;
    uint16_t q0[4], q1[4], q2[4];
#pragma unroll
    for (int j = 0; j < 4; j++) split3(s[kq * 4 + j][onl], q0[j], q1[j], q2[j]);
    size_t base = (size_t)(n0 + onl) * 1024 + k0 + kq * 4;
    *(uint2*)(colh + base)                   = make_uint2(pack2(q0[0], q0[1]), pack2(q0[2], q0[3]));
    *(uint2*)(colh + planeStride + base)     = make_uint2(pack2(q1[0], q1[1]), pack2(q1[2], q1[3]));
    *(uint2*)(colh + 2 * planeStride + base) = make_uint2(pack2(q2[0], q2[1]), pack2(q2[2], q2[3]));
}

// ---------------------------------------------------------------------------
// unified weight prep (single launch): y<11 round/pad layers, y 11-14 dt1
// parities, y==15 dt2.
// ---------------------------------------------------------------------------
struct PrepArgs {
    const float* w[11];
    const float* dt1;
    const float* dt2;
};

__global__ void prep_weights(PrepArgs pa, __nv_bfloat16* __restrict__ wtsh,
                             float* __restrict__ wpk)
{
    const int y = blockIdx.y;
    const int i = blockIdx.x * 256 + threadIdx.x;
    if (y < 11) {
        const int Ks[11] = {48, 4096, 2304, 256, 2304, 256, 2304, 256, 2304, 256, 256};
        const int Kp[11] = {64, 4096, 2304, 256, 2304, 256, 2304, 256, 2304, 256, 256};
        const int Ms[11] = {256, 256, 256, 256, 256, 256, 256, 256, 256, 256, 512};
        const int Of[11] = {OFF_C1, OFF_C2, OFF_ER1A, OFF_ER1B, OFF_ER2A, OFF_ER2B,
                            OFF_DR1A, OFF_DR1B, OFF_DR2A, OFF_DR2B, OFF_EMB};
        int K = Ks[y], K_pad = Kp[y], M = Ms[y], off = Of[y];
        if (i >= M * K_pad) return;
        int m = i / K_pad, k = i - m * K_pad;
        float v = (k < K) ? pa.w[y][m * K + k] : 0.f;
        uint16_t q0, q1, q2;
        split3(v, q0, q1, q2);
        wtsh[off + i] = __ushort_as_bfloat16(q0);
        wtsh[WPLANE + off + i] = __ushort_as_bfloat16(q1);
        wtsh[2 * WPLANE + off + i] = __ushort_as_bfloat16(q2);
    } else if (y < 15) {
        if (i >= 262144) return;
        int par = y - 11;
        int ry = par >> 1, rx = par & 1;
        int co = i >> 10;
        int k = i & 1023;
        int ci = k >> 2;
        int a = (k >> 1) & 1, bb = k & 1;
        float v = pa.dt1[((ci * 256 + co) * 4 + (3 - ry - 2 * a)) * 4 + (3 - rx - 2 * bb)];
        uint16_t q0, q1, q2;
        split3(v, q0, q1, q2);
        int off = OFF_DT1 + par * 262144;
        wtsh[off + i] = __ushort_as_bfloat16(q0);
        wtsh[WPLANE + off + i] = __ushort_as_bfloat16(q1);
        wtsh[2 * WPLANE + off + i] = __ushort_as_bfloat16(q2);
    } else {
        if (i >= 12288) return;
        int tap = i & 3;
        int par = (i >> 2) & 3;
        int co = (i >> 4) % 3;
        int ci = i / 48;
        int a = tap >> 1, bb = tap & 1;
        int ry = par >> 1, rx = par & 1;
        wpk[i] = pa.dt2[((ci * 3 + co) * 4 + (3 - ry - 2 * a)) * 4 + (3 - rx - 2 * bb)];
    }
}

// ---------------------------------------------------------------------------
// VQ kernels
// ---------------------------------------------------------------------------
__global__ void vq_enorm(const float* __restrict__ e, float* __restrict__ en)
{
    __shared__ float s[256];
    int k = blockIdx.x;
    float v = e[k * 256 + threadIdx.x];
    s[threadIdx.x] = v * v;
    __syncthreads();
    for (int off = 128; off > 0; off >>= 1) {
        if (threadIdx.x < off) s[threadIdx.x] += s[threadIdx.x + off];
        __syncthreads();
    }
    if (threadIdx.x == 0) en[k] = s[0];
}

__global__ void vq_argmin(const float* __restrict__ S, const float* __restrict__ en,
                          int* __restrict__ idx)
{
    int n = blockIdx.x * 256 + threadIdx.x;
    if (n >= N_LAT) return;
    float best = 3.4e38f;
    int bi = 0;
    for (int k = 0; k < 512; k++) {
        float v = en[k] - 2.f * S[k * N_LAT + n];
        if (v < best) { best = v; bi = k; }
    }
    idx[n] = bi;
}

// gather z_q (NCHW, exact fp32 embed) + deterministic loss partials
__global__ void vq_gather(const float* __restrict__ ze, const float* __restrict__ embed,
                          const int* __restrict__ idx, float* __restrict__ zq,
                          float* __restrict__ part)
{
    __shared__ float s[256];
    int tx = threadIdx.x & 31, ty = threadIdx.x >> 5;
    int n = blockIdx.x * 32 + tx;
    int id = idx[n];
    int b = n >> 10, p = n & 1023;
    float acc = 0.f;
    for (int d = ty; d < 256; d += 8) {
        float e = embed[id * 256 + d];
        float z = ze[(b * 256 + d) * 1024 + p];
        zq[(b * 256 + d) * 1024 + p] = e;
        float df = z - e;
        acc += df * df;
    }
    s[threadIdx.x] = acc;
    __syncthreads();
    for (int off = 128; off > 0; off >>= 1) {
        if (threadIdx.x < off) s[threadIdx.x] += s[threadIdx.x + off];
        __syncthreads();
    }
    if (threadIdx.x == 0) part[blockIdx.x] = s[0];
}

__global__ void loss_write(const float* __restrict__ part, float* __restrict__ out, int out_size)
{
    __shared__ float s[256];
    float v = 0.f;
    for (int i = threadIdx.x; i < 1024; i += 256) v += part[i];
    s[threadIdx.x] = v;
    __syncthreads();
    for (int off = 128; off > 0; off >>= 1) {
        if (threadIdx.x < off) s[threadIdx.x] += s[threadIdx.x + off];
        __syncthreads();
    }
    if (threadIdx.x == 0 && out_size >= 2) {
        float L = s[0] / 32768.f;
        out[out_size - 2] = L;
        out[out_size - 1] = L;
    }
}

// ---------------------------------------------------------------------------
// deconv2 (256 -> 3, k4 s2 p1) + sigmoid, direct parity kernel (fp32).
// ---------------------------------------------------------------------------
__global__ __launch_bounds__(256) void deconv2_sig(
    const float* __restrict__ in, const float* __restrict__ wpk,
    const float* __restrict__ bias, float* __restrict__ out)
{
    __shared__ float ins[2][34][36];
    __shared__ float wsc[96];
    const int tid = threadIdx.x;
    const int b = blockIdx.y;
    const int tileY = (blockIdx.x >> 1) << 5;
    const int tileX = (blockIdx.x & 1) << 5;
    const int lmy = (tid >> 4) << 1;
    const int lmx = (tid & 15) << 1;

    float acc[48];
#pragma unroll
    for (int i = 0; i < 48; i++) acc[i] = 0.f;

    const float* inb = in + (size_t)b * 256 * 4096;

    for (int c0 = 0; c0 < 256; c0 += 2) {
        __syncthreads();
        for (int e = tid; e < 2 * 34 * 34; e += 256) {
            int cc = (e >= 1156) ? 1 : 0;
            int rem = e - cc * 1156;
            int r = rem / 34, c = rem - r * 34;
            int gy = tileY - 1 + r, gx = tileX - 1 + c;
            float v = 0.f;
            if ((unsigned)gy < 64u && (unsigned)gx < 64u)
                v = inb[(c0 + cc) * 4096 + (gy << 6) + gx];
            ins[cc][r][c] = v;
        }
        if (tid < 96) wsc[tid] = wpk[c0 * 48 + tid];
        __syncthreads();
#pragma unroll
        for (int cc = 0; cc < 2; cc++) {
            float r4[4][4];
#pragma unroll
            for (int dy = 0; dy < 4; dy++)
#pragma unroll
                for (int dx = 0; dx < 4; dx++)
                    r4[dy][dx] = ins[cc][lmy + dy][lmx + dx];
#pragma unroll
            for (int co = 0; co < 3; co++)
#pragma unroll
                for (int par = 0; par < 4; par++) {
                    int ry = par >> 1, rx = par & 1;
                    float4 w = *(const float4*)&wsc[cc * 48 + co * 16 + par * 4];
#pragma unroll
                    for (int dmy = 0; dmy < 2; dmy++)
#pragma unroll
                        for (int dmx = 0; dmx < 2; dmx++) {
                            acc[((dmy * 2 + dmx) * 3 + co) * 4 + par] +=
                                  w.x * r4[dmy + ry][dmx + rx]
                                + w.y * r4[dmy + ry][dmx + 1 + rx]
                                + w.z * r4[dmy + 1 + ry][dmx + rx]
                                + w.w * r4[dmy + 1 + ry][dmx + 1 + rx];
                        }
                }
        }
    }

#pragma unroll
    for (int dmy = 0; dmy < 2; dmy++)
#pragma unroll
        for (int dmx = 0; dmx < 2; dmx++)
#pragma unroll
            for (int co = 0; co < 3; co++)
#pragma unroll
                for (int par = 0; par < 4; par++) {
                    int ry = par >> 1, rx = par & 1;
                    int my = tileY + lmy + dmy, mx = tileX + lmx + dmx;
                    int oy = (my << 1) + ry, ox = (mx << 1) + rx;
                    float v = acc[((dmy * 2 + dmx) * 3 + co) * 4 + par] + bias[co];
                    v = 1.f / (1.f + expf(-v));
                    out[((b * 3 + co) << 14) + (oy << 7) + ox] = v;
                }
}

// ---------------------------------------------------------------------------
// launcher
// ---------------------------------------------------------------------------
extern "C" void kernel_launch(void* const* d_in, const int* in_sizes, int n_in,
                              void* d_out, int out_size)
{
    const float* x     = (const float*)d_in[0];
    const float* embed = (const float*)d_in[1];
    const float* dt1_b = (const float*)d_in[13];
    const float* dt2_b = (const float*)d_in[15];
    float* out = (float*)d_out;

    __nv_bfloat16 *colh, *wtsh;
    float *h1, *h2, *tb, *ab, *ze, *zq, *bb, *S, *d1, *enrm, *wpk, *part;
    int* idxp;
    cudaGetSymbolAddress((void**)&colh, g_colh);
    cudaGetSymbolAddress((void**)&wtsh, g_wtsh);
    cudaGetSymbolAddress((void**)&h1,   g_h1);
    cudaGetSymbolAddress((void**)&h2,   g_h2);
    cudaGetSymbolAddress((void**)&tb,   g_t);
    cudaGetSymbolAddress((void**)&ab,   g_a);
    cudaGetSymbolAddress((void**)&ze,   g_ze);
    cudaGetSymbolAddress((void**)&zq,   g_zq);
    cudaGetSymbolAddress((void**)&bb,   g_b2);
    cudaGetSymbolAddress((void**)&S,    g_s);
    cudaGetSymbolAddress((void**)&d1,   g_d1);
    cudaGetSymbolAddress((void**)&enrm, g_enorm);
    cudaGetSymbolAddress((void**)&wpk,  g_wpk);
    cudaGetSymbolAddress((void**)&part, g_part);
    cudaGetSymbolAddress((void**)&idxp, g_idx);

    cudaFuncSetAttribute(gemm_bf16x, cudaFuncAttributeMaxDynamicSharedMemorySize, GEMM_SMEM_H);

    // ---- weight prep: single launch ----
    PrepArgs pa;
    pa.w[0]  = (const float*)d_in[2];   // e_w1
    pa.w[1]  = (const float*)d_in[3];   // e_w2
    pa.w[2]  = (const float*)d_in[4];   // e_r1a
    pa.w[3]  = (const float*)d_in[5];   // e_r1b
    pa.w[4]  = (const float*)d_in[6];   // e_r2a
    pa.w[5]  = (const float*)d_in[7];   // e_r2b
    pa.w[6]  = (const float*)d_in[8];   // d_r1a
    pa.w[7]  = (const float*)d_in[9];   // d_r1b
    pa.w[8]  = (const float*)d_in[10];  // d_r2a
    pa.w[9]  = (const float*)d_in[11];  // d_r2b
    pa.w[10] = embed;
    pa.dt1   = (const float*)d_in[12];
    pa.dt2   = (const float*)d_in[14];
    prep_weights<<<dim3(4096, 16), 256>>>(pa, wtsh, wpk);

    // ---- encoder conv1: 3 -> 256, k4 s2 p1, 128 -> 64, relu (K_pad=64), full ----
    im2colT_conv_h<<<dim3(N_HALF / 32, 2), 256>>>(x, colh, (size_t)N_HALF * 64,
        3, 128, 128, 12, 6, 16, 4, 2, 1, 48, 64);
    gemm_bf16x<<<dim3(2, N_HALF / 128), 256, GEMM_SMEM_H>>>(
        wtsh + OFF_C1, WPLANE, colh, (size_t)N_HALF * 64, h1, 256, 64, 1,
        12, 6, 64, 64, 1, 1, 0, 0, nullptr, nullptr, 1);

    // ---- encoder conv2: 256 -> 256, k4 s2 p1, 64 -> 32, relu, full ----
    im2colT_conv_h<<<dim3(N_LAT / 32, 128), 256>>>(h1, colh, (size_t)N_LAT * 4096,
        256, 64, 64, 10, 5, 16, 4, 2, 1, 4096, 4096);
    gemm_bf16x<<<dim3(2, N_LAT / 128), 256, GEMM_SMEM_H>>>(
        wtsh + OFF_C2, WPLANE, colh, (size_t)N_LAT * 4096, h2, 256, 4096, 1,
        10, 5, 32, 32, 1, 1, 0, 0, nullptr, nullptr, 1);

    // ---- residual block: 3x3 relu -> 1x1 + residual ----
    auto res = [&](const float* src, int offA, int offB, float* tmp, float* dst, int full) {
        im2colT_conv_h<<<dim3(N_LAT / 32, 72), 256>>>(src, colh, (size_t)N_LAT * 2304,
            256, 32, 32, 10, 5, 9, 3, 1, 1, 2304, 2304);
        gemm_bf16x<<<dim3(2, N_LAT / 128), 256, GEMM_SMEM_H>>>(
            wtsh + offA, WPLANE, colh, (size_t)N_LAT * 2304, tmp, 256, 2304, full,
            10, 5, 32, 32, 1, 1, 0, 0, nullptr, nullptr, 1);
        im2colT_conv_h<<<dim3(N_LAT / 32, 8), 256>>>(tmp, colh, (size_t)N_LAT * 256,
            256, 32, 32, 10, 5, 1, 1, 1, 0, 256, 256);
        gemm_bf16x<<<dim3(2, N_LAT / 128), 256, GEMM_SMEM_H>>>(
            wtsh + offB, WPLANE, colh, (size_t)N_LAT * 256, dst, 256, 256, full,
            10, 5, 32, 32, 1, 1, 0, 0, nullptr, src, 0);
    };
    res(h2, OFF_ER1A, OFF_ER1B, tb, ab, 1);
    res(ab, OFF_ER2A, OFF_ER2B, tb, ze, 1);

    // ---- vector quantisation (full precision scores) ----
    im2colT_conv_h<<<dim3(N_LAT / 32, 8), 256>>>(ze, colh, (size_t)N_LAT * 256,
        256, 32, 32, 10, 5, 1, 1, 1, 0, 256, 256);
    vq_enorm<<<512, 256>>>(embed, enrm);
    gemm_bf16x<<<dim3(4, N_LAT / 128), 256, GEMM_SMEM_H>>>(
        wtsh + OFF_EMB, WPLANE, colh, (size_t)N_LAT * 256, S, 512, 256, 1,
        15, 15, 1, N_LAT, 1, 1, 0, 0, nullptr, nullptr, 0);
    vq_argmin<<<N_LAT / 256, 256>>>(S, enrm, idxp);
    vq_gather<<<1024, 256>>>(ze, embed, idxp, zq, part);

    // ---- decoder residual blocks (3-product path) ----
    res(zq, OFF_DR1A, OFF_DR1B, tb, ab, 0);
    res(ab, OFF_DR2A, OFF_DR2B, tb, bb, 0);

    // ---- deconv1: 256 -> 256, k4 s2 p1, 32 -> 64, +bias, relu (4 parity GEMMs) ----
    for (int par = 0; par < 4; par++) {
        int ry = par >> 1, rx = par & 1;
        im2colT_dec_h<<<dim3(N_LAT / 32, 32), 256>>>(bb, colh, (size_t)N_LAT * 1024, ry, rx);
        gemm_bf16x<<<dim3(2, N_LAT / 128), 256, GEMM_SMEM_H>>>(
            wtsh + OFF_DT1 + par * 262144, WPLANE, colh, (size_t)N_LAT * 1024, d1, 256, 1024, 0,
            10, 5, 64, 64, 2, 2, ry, rx, dt1_b, nullptr, 1);
    }

    // ---- deconv2: 256 -> 3, k4 s2 p1, 64 -> 128, +bias, sigmoid ----
    deconv2_sig<<<dim3(4, 32), 256>>>(d1, wpk, dt2_b, out);

    // ---- losses ----
    loss_write<<<1, 256>>>(part, out, out_size);
}

// round 10
// speedup vs baseline: 1.3634x; 1.3634x over previous
#include <cuda_runtime.h>
#include <cuda_bf16.h>
#include <math.h>
#include <stdint.h>

// ---------------------------------------------------------------------------
// VQ-VAE forward — bf16 split mma.sync GEMM.
// 2-plane/3-product for bulk layers; 3-plane/6-product for conv1 + VQ scores.
// B=32, CIN=3, IMG=128, D=256, K=512. Latent 32x32.
// ---------------------------------------------------------------------------

#define N_LAT 32768      // B * 32 * 32
#define N_HALF 131072    // B * 64 * 64
#define WPLANE 5242880   // weight plane stride (elements)

// ---- scratch (device globals; allocation is forbidden) ----
static __device__ __nv_bfloat16 g_colh[402653184]; // 3 planes x 134217728 (max N*K_pad)
static __device__ __nv_bfloat16 g_wtsh[15728640];  // 3 planes x 5242880
static __device__ float g_h1[33554432];    // (32,256,64,64)
static __device__ float g_h2[8388608];     // (32,256,32,32)
static __device__ float g_t[8388608];
static __device__ float g_a[8388608];
static __device__ float g_ze[8388608];
static __device__ float g_zq[8388608];
static __device__ float g_b2[8388608];
static __device__ float g_s[16777216];     // (512, 32768) VQ scores
static __device__ float g_d1[33554432];    // (32,256,64,64) deconv1 out
static __device__ int   g_idx[32768];
static __device__ float g_enorm[512];
static __device__ float g_wpk[12288];      // deconv2 repacked weights (fp32)
static __device__ float g_part[1024];      // loss partials

// weight offsets within one plane (elements)
#define OFF_C1    0          // 256 x 64
#define OFF_C2    16384      // 256 x 4096
#define OFF_ER1A  1064960    // 256 x 2304
#define OFF_ER1B  1654784    // 256 x 256
#define OFF_ER2A  1720320
#define OFF_ER2B  2310144
#define OFF_DR1A  2375680
#define OFF_DR1B  2965504
#define OFF_DR2A  3031040
#define OFF_DR2B  3620864
#define OFF_EMB   3686400    // 512 x 256
#define OFF_DT1   3817472    // 4 x (256 x 1024)

// ---------------------------------------------------------------------------
// helpers
// ---------------------------------------------------------------------------
__device__ __forceinline__ uint32_t smem_u32(const void* p) {
    uint32_t a;
    asm("{ .reg .u64 t; cvta.to.shared.u64 t, %1; cvt.u32.u64 %0, t; }" : "=r"(a) : "l"(p));
    return a;
}

__device__ __forceinline__ void cp16(uint32_t dst, const void* src) {
    asm volatile("cp.async.cg.shared.global [%0], [%1], 16;" :: "r"(dst), "l"(src));
}

__device__ __forceinline__ uint32_t lds32(uint32_t a) {
    uint32_t v;
    asm volatile("ld.shared.b32 %0, [%1];" : "=r"(v) : "r"(a));
    return v;
}

__device__ __forceinline__ void mma16(float* d, const uint32_t* a, const uint32_t* b) {
    asm volatile(
        "mma.sync.aligned.m16n8k16.row.col.f32.bf16.bf16.f32 "
        "{%0,%1,%2,%3}, {%4,%5,%6,%7}, {%8,%9}, {%0,%1,%2,%3};"
        : "+f"(d[0]), "+f"(d[1]), "+f"(d[2]), "+f"(d[3])
        : "r"(a[0]), "r"(a[1]), "r"(a[2]), "r"(a[3]), "r"(b[0]), "r"(b[1]));
}

// 3-way bf16 split: v = b0 + b1 + b2 (+ O(2^-27 v))
__device__ __forceinline__ void split3(float v, uint16_t& q0, uint16_t& q1, uint16_t& q2) {
    __nv_bfloat16 h0 = __float2bfloat16(v);
    float r1 = v - __bfloat162float(h0);
    __nv_bfloat16 h1 = __float2bfloat16(r1);
    float r2 = r1 - __bfloat162float(h1);
    __nv_bfloat16 h2 = __float2bfloat16(r2);
    q0 = __bfloat16_as_ushort(h0);
    q1 = __bfloat16_as_ushort(h1);
    q2 = __bfloat16_as_ushort(h2);
}

// 2-way bf16 split: v = b0 + b1 (+ O(2^-17 v))
__device__ __forceinline__ void split2(float v, uint16_t& q0, uint16_t& q1) {
    __nv_bfloat16 h0 = __float2bfloat16(v);
    float r1 = v - __bfloat162float(h0);
    __nv_bfloat16 h1 = __float2bfloat16(r1);
    q0 = __bfloat16_as_ushort(h0);
    q1 = __bfloat16_as_ushort(h1);
}

__device__ __forceinline__ uint32_t pack2(uint16_t lo, uint16_t hi) {
    return (uint32_t)lo | ((uint32_t)hi << 16);
}

// ---------------------------------------------------------------------------
// bf16x GEMM:  C[m][n] = sum_k A[m][k] * Bc[n][k]
//   A3/B3: bf16 planes [M][K_pad] / [N][K_pad], plane strides aStride/bStride.
//   full=1: 3 planes, 6 products (fp32-grade); full=0: 2 planes, 3 products.
//   CTA 128(M) x 128(N), 8 warps (warp 64x32), k-step 32, 3-stage cp.async.
//   Grid: (M/128, N/128)  — bm = blockIdx.x<<7, bn = blockIdx.y<<7.
//   Smem rows: 80B stride (64B data + 16B pad).
//   Epilogue: conv-style NCHW scatter with bias/resid/relu.
// ---------------------------------------------------------------------------
#define GEMM_SMEM_H 184320   // 3 stages * 6 plane slots * 128 rows * 80 B

__global__ void __launch_bounds__(256, 1) gemm_bf16x(
    const __nv_bfloat16* __restrict__ A3, size_t aStride,
    const __nv_bfloat16* __restrict__ B3, size_t bStride,
    float* __restrict__ C, int M, int K_pad, int full,
    int logHW, int logW, int Hout, int Wout,
    int sy, int sx, int ry, int rx,
    const float* __restrict__ bias, const float* __restrict__ resid, int relu)
{
    extern __shared__ char smc[];
    const int tid = threadIdx.x;
    const int lane = tid & 31, warp = tid >> 5;
    const int g = lane >> 2, t = lane & 3;
    const int wm = (warp >> 2) << 6;   // 0/64
    const int wn = (warp & 3) << 5;    // 0..96
    const int bm = blockIdx.x << 7;    // M-tile on x (gridDim.x = M/128)
    const int bn = blockIdx.y << 7;    // N-tile on y
    const uint32_t sb = smem_u32(smc);
    const int nk = K_pad >> 5;
    const int np = full ? 3 : 2;

    float acc[4][4][4];
#pragma unroll
    for (int i = 0; i < 4; i++)
#pragma unroll
        for (int j = 0; j < 4; j++)
#pragma unroll
            for (int q = 0; q < 4; q++) acc[i][j][q] = 0.f;

    // stage layout: A plane p at p*10240, B plane p at 30720 + p*10240
    auto loadStage = [&](int it, int slot) {
        const int k0 = it << 5;
        const uint32_t st = sb + slot * 61440;
        const int groups = full ? 12 : 8;
#pragma unroll
        for (int j = 0; j < 12; j++) {
            if (j >= groups) break;
            int c = j * 256 + tid;
            int pg0 = c >> 9;
            int pg = full ? pg0 : ((pg0 & 1) + ((pg0 >> 1) * 3));  // 0,1,3,4
            int r  = (c >> 2) & 127;
            int u  = c & 3;
            const __nv_bfloat16* src;
            if (pg < 3) src = A3 + (size_t)pg * aStride + (size_t)(bm + r) * K_pad + k0 + u * 8;
            else        src = B3 + (size_t)(pg - 3) * bStride + (size_t)(bn + r) * K_pad + k0 + u * 8;
            cp16(st + pg * 10240 + r * 80 + u * 16, src);
        }
        asm volatile("cp.async.commit_group;");
    };

    loadStage(0, 0);
    if (nk > 1) loadStage(1, 1);

    for (int it = 0; it < nk; it++) {
        if (it <= nk - 2) asm volatile("cp.async.wait_group 1;");
        else              asm volatile("cp.async.wait_group 0;");
        __syncthreads();
        if (it + 2 < nk) loadStage(it + 2, (it + 2) % 3);

        const uint32_t st = sb + (it % 3) * 61440;
#pragma unroll
        for (int h = 0; h < 2; h++) {
            // ---- B fragments: 4 n-tiles x np planes ----
            uint32_t bf[4][3][2];
#pragma unroll
            for (int nt = 0; nt < 4; nt++)
#pragma unroll
                for (int p = 0; p < 3; p++) {
                    if (p >= np) break;
                    uint32_t ad = st + 30720 + p * 10240
                                + (wn + (nt << 3) + g) * 80 + (h << 5) + (t << 2);
                    bf[nt][p][0] = lds32(ad);
                    bf[nt][p][1] = lds32(ad + 16);
                }
            // ---- per m-tile: A fragments + products ----
#pragma unroll
            for (int mt = 0; mt < 4; mt++) {
                uint32_t af[3][4];
#pragma unroll
                for (int p = 0; p < 3; p++) {
                    if (p >= np) break;
                    uint32_t ad = st + p * 10240
                                + (wm + (mt << 4) + g) * 80 + (h << 5) + (t << 2);
                    af[p][0] = lds32(ad);
                    af[p][1] = lds32(ad + 640);        // row +8
                    af[p][2] = lds32(ad + 16);         // k +8
                    af[p][3] = lds32(ad + 656);
                }
#pragma unroll
                for (int nt = 0; nt < 4; nt++) mma16(acc[mt][nt], af[0], bf[nt][0]);
#pragma unroll
                for (int nt = 0; nt < 4; nt++) mma16(acc[mt][nt], af[1], bf[nt][0]);
#pragma unroll
                for (int nt = 0; nt < 4; nt++) mma16(acc[mt][nt], af[0], bf[nt][1]);
                if (full) {
#pragma unroll
                    for (int nt = 0; nt < 4; nt++) mma16(acc[mt][nt], af[1], bf[nt][1]);
#pragma unroll
                    for (int nt = 0; nt < 4; nt++) mma16(acc[mt][nt], af[2], bf[nt][0]);
#pragma unroll
                    for (int nt = 0; nt < 4; nt++) mma16(acc[mt][nt], af[0], bf[nt][2]);
                }
            }
        }
    }

    // ---- epilogue: NCHW conv scatter ----
    const int HWout = Hout * Wout;
    const int hwmask = (1 << logHW) - 1;
    const int wmask = (1 << logW) - 1;
#pragma unroll
    for (int mt = 0; mt < 4; mt++) {
#pragma unroll
        for (int half = 0; half < 2; half++) {
            int m = bm + wm + (mt << 4) + g + (half << 3);
            float bv = bias ? bias[m] : 0.f;
            int mb = m * HWout;
#pragma unroll
            for (int nt = 0; nt < 4; nt++) {
                int n = bn + wn + (nt << 3) + (t << 1);
                int bimg = n >> logHW;
                int p = n & hwmask;
                int yy = p >> logW, xx = p & wmask;
                int o = bimg * M * HWout + mb + (yy * sy + ry) * Wout + xx * sx + rx;
                float v0 = acc[mt][nt][half * 2 + 0] + bv;
                float v1 = acc[mt][nt][half * 2 + 1] + bv;
                if (resid) { v0 += resid[o]; v1 += resid[o + sx]; }
                if (relu) { v0 = fmaxf(v0, 0.f); v1 = fmaxf(v1, 0.f); }
                C[o] = v0;
                C[o + sx] = v1;
            }
        }
    }
}

// ---------------------------------------------------------------------------
// im2colT: build nplanes bf16 planes of colT[N][K_pad], 32x32 staged transpose.
// ---------------------------------------------------------------------------
__global__ void im2colT_conv_h(const float* __restrict__ in, __nv_bfloat16* __restrict__ colh,
                               size_t planeStride, int nplanes,
                               int C, int Hin, int Win, int logHW, int logW,
                               int RS, int S, int stride, int pad, int K, int K_pad)
{
    __shared__ float s[32][33];
    const int tid = threadIdx.x;
    const int n0 = blockIdx.x << 5, k0 = blockIdx.y << 5;
    const int nl = tid & 31, kr = tid >> 5;
    const int n = n0 + nl;
    const int b = n >> logHW;
    const int p = n & ((1 << logHW) - 1);
    const int oy = p >> logW, ox = p & ((1 << logW) - 1);
#pragma unroll
    for (int pass = 0; pass < 4; pass++) {
        int k = k0 + pass * 8 + kr;
        float v = 0.f;
        if (k < K) {
            int ci = k / RS;
            int rs = k - ci * RS;
            int r = rs / S, ss = rs - r * S;
            int iy = oy * stride - pad + r;
            int ix = ox * stride - pad + ss;
            if ((unsigned)iy < (unsigned)Hin && (unsigned)ix < (unsigned)Win)
                v = in[((b * C + ci) * Hin + iy) * Win + ix];
        }
        s[pass * 8 + kr][nl] = v;
    }
    __syncthreads();
    const int onl = tid >> 3, kq = tid & 7;
    size_t base = (size_t)(n0 + onl) * K_pad + k0 + kq * 4;
    if (nplanes == 2) {
        uint16_t q0[4], q1[4];
#pragma unroll
        for (int j = 0; j < 4; j++) split2(s[kq * 4 + j][onl], q0[j], q1[j]);
        *(uint2*)(colh + base)               = make_uint2(pack2(q0[0], q0[1]), pack2(q0[2], q0[3]));
        *(uint2*)(colh + planeStride + base) = make_uint2(pack2(q1[0], q1[1]), pack2(q1[2], q1[3]));
    } else {
        uint16_t q0[4], q1[4], q2[4];
#pragma unroll
        for (int j = 0; j < 4; j++) split3(s[kq * 4 + j][onl], q0[j], q1[j], q2[j]);
        *(uint2*)(colh + base)                   = make_uint2(pack2(q0[0], q0[1]), pack2(q0[2], q0[3]));
        *(uint2*)(colh + planeStride + base)     = make_uint2(pack2(q1[0], q1[1]), pack2(q1[2], q1[3]));
        *(uint2*)(colh + 2 * planeStride + base) = make_uint2(pack2(q2[0], q2[1]), pack2(q2[2], q2[3]));
    }
}

// im2colT for transposed-conv parity class (ry,rx): k = ci*4 + a*2 + bb (2 planes)
__global__ void im2colT_dec_h(const float* __restrict__ in, __nv_bfloat16* __restrict__ colh,
                              size_t planeStride, int ry, int rx)
{
    __shared__ float s[32][33];
    const int tid = threadIdx.x;
    const int n0 = blockIdx.x << 5, k0 = blockIdx.y << 5;
    const int nl = tid & 31, kr = tid >> 5;
    const int n = n0 + nl;
    const int b = n >> 10;
    const int p = n & 1023;
    const int my = p >> 5, mx = p & 31;
#pragma unroll
    for (int pass = 0; pass < 4; pass++) {
        int k = k0 + pass * 8 + kr;
        int ci = k >> 2;
        int a = (k >> 1) & 1, bb = k & 1;
        int iy = my + a - 1 + ry, ix = mx + bb - 1 + rx;
        float v = 0.f;
        if ((unsigned)iy < 32u && (unsigned)ix < 32u)
            v = in[((b * 256 + ci) * 32 + iy) * 32 + ix];
        s[pass * 8 + kr][nl] = v;
    }
    __syncthreads();
    const int onl = tid >> 3, kq = tid & 7;
    uint16_t q0[4], q1[4];
#pragma unroll
    for (int j = 0; j < 4; j++) split2(s[kq * 4 + j][onl], q0[j], q1[j]);
    size_t base = (size_t)(n0 + onl) * 1024 + k0 + kq * 4;
    *(uint2*)(colh + base)               = make_uint2(pack2(q0[0], q0[1]), pack2(q0[2], q0[3]));
    *(uint2*)(colh + planeStride + base) = make_uint2(pack2(q1[0], q1[1]), pack2(q1[2], q1[3]));
}

// ---------------------------------------------------------------------------
// unified weight prep (single launch): y<11 round/pad layers, y 11-14 dt1
// parities, y==15 dt2.
// ---------------------------------------------------------------------------
struct PrepArgs {
    const float* w[11];
    const float* dt1;
    const float* dt2;
};

__global__ void prep_weights(PrepArgs pa, __nv_bfloat16* __restrict__ wtsh,
                             float* __restrict__ wpk)
{
    const int y = blockIdx.y;
    const int i = blockIdx.x * 256 + threadIdx.x;
    if (y < 11) {
        const int Ks[11] = {48, 4096, 2304, 256, 2304, 256, 2304, 256, 2304, 256, 256};
        const int Kp[11] = {64, 4096, 2304, 256, 2304, 256, 2304, 256, 2304, 256, 256};
        const int Ms[11] = {256, 256, 256, 256, 256, 256, 256, 256, 256, 256, 512};
        const int Of[11] = {OFF_C1, OFF_C2, OFF_ER1A, OFF_ER1B, OFF_ER2A, OFF_ER2B,
                            OFF_DR1A, OFF_DR1B, OFF_DR2A, OFF_DR2B, OFF_EMB};
        int K = Ks[y], K_pad = Kp[y], M = Ms[y], off = Of[y];
        if (i >= M * K_pad) return;
        int m = i / K_pad, k = i - m * K_pad;
        float v = (k < K) ? pa.w[y][m * K + k] : 0.f;
        uint16_t q0, q1, q2;
        split3(v, q0, q1, q2);
        wtsh[off + i] = __ushort_as_bfloat16(q0);
        wtsh[WPLANE + off + i] = __ushort_as_bfloat16(q1);
        wtsh[2 * WPLANE + off + i] = __ushort_as_bfloat16(q2);
    } else if (y < 15) {
        if (i >= 262144) return;
        int par = y - 11;
        int ry = par >> 1, rx = par & 1;
        int co = i >> 10;
        int k = i & 1023;
        int ci = k >> 2;
        int a = (k >> 1) & 1, bb = k & 1;
        float v = pa.dt1[((ci * 256 + co) * 4 + (3 - ry - 2 * a)) * 4 + (3 - rx - 2 * bb)];
        uint16_t q0, q1, q2;
        split3(v, q0, q1, q2);
        int off = OFF_DT1 + par * 262144;
        wtsh[off + i] = __ushort_as_bfloat16(q0);
        wtsh[WPLANE + off + i] = __ushort_as_bfloat16(q1);
        wtsh[2 * WPLANE + off + i] = __ushort_as_bfloat16(q2);
    } else {
        if (i >= 12288) return;
        int tap = i & 3;
        int par = (i >> 2) & 3;
        int co = (i >> 4) % 3;
        int ci = i / 48;
        int a = tap >> 1, bb = tap & 1;
        int ry = par >> 1, rx = par & 1;
        wpk[i] = pa.dt2[((ci * 3 + co) * 4 + (3 - ry - 2 * a)) * 4 + (3 - rx - 2 * bb)];
    }
}

// ---------------------------------------------------------------------------
// VQ kernels
// ---------------------------------------------------------------------------
__global__ void vq_enorm(const float* __restrict__ e, float* __restrict__ en)
{
    __shared__ float s[256];
    int k = blockIdx.x;
    float v = e[k * 256 + threadIdx.x];
    s[threadIdx.x] = v * v;
    __syncthreads();
    for (int off = 128; off > 0; off >>= 1) {
        if (threadIdx.x < off) s[threadIdx.x] += s[threadIdx.x + off];
        __syncthreads();
    }
    if (threadIdx.x == 0) en[k] = s[0];
}

__global__ void vq_argmin(const float* __restrict__ S, const float* __restrict__ en,
                          int* __restrict__ idx)
{
    int n = blockIdx.x * 256 + threadIdx.x;
    if (n >= N_LAT) return;
    float best = 3.4e38f;
    int bi = 0;
    for (int k = 0; k < 512; k++) {
        float v = en[k] - 2.f * S[k * N_LAT + n];
        if (v < best) { best = v; bi = k; }
    }
    idx[n] = bi;
}

// gather z_q (NCHW, exact fp32 embed) + deterministic loss partials
__global__ void vq_gather(const float* __restrict__ ze, const float* __restrict__ embed,
                          const int* __restrict__ idx, float* __restrict__ zq,
                          float* __restrict__ part)
{
    __shared__ float s[256];
    int tx = threadIdx.x & 31, ty = threadIdx.x >> 5;
    int n = blockIdx.x * 32 + tx;
    int id = idx[n];
    int b = n >> 10, p = n & 1023;
    float acc = 0.f;
    for (int d = ty; d < 256; d += 8) {
        float e = embed[id * 256 + d];
        float z = ze[(b * 256 + d) * 1024 + p];
        zq[(b * 256 + d) * 1024 + p] = e;
        float df = z - e;
        acc += df * df;
    }
    s[threadIdx.x] = acc;
    __syncthreads();
    for (int off = 128; off > 0; off >>= 1) {
        if (threadIdx.x < off) s[threadIdx.x] += s[threadIdx.x + off];
        __syncthreads();
    }
    if (threadIdx.x == 0) part[blockIdx.x] = s[0];
}

__global__ void loss_write(const float* __restrict__ part, float* __restrict__ out, int out_size)
{
    __shared__ float s[256];
    float v = 0.f;
    for (int i = threadIdx.x; i < 1024; i += 256) v += part[i];
    s[threadIdx.x] = v;
    __syncthreads();
    for (int off = 128; off > 0; off >>= 1) {
        if (threadIdx.x < off) s[threadIdx.x] += s[threadIdx.x + off];
        __syncthreads();
    }
    if (threadIdx.x == 0 && out_size >= 2) {
        float L = s[0] / 32768.f;
        out[out_size - 2] = L;
        out[out_size - 1] = L;
    }
}

// ---------------------------------------------------------------------------
// deconv2 (256 -> 3, k4 s2 p1) + sigmoid, direct parity kernel (fp32).
// ---------------------------------------------------------------------------
__global__ __launch_bounds__(256) void deconv2_sig(
    const float* __restrict__ in, const float* __restrict__ wpk,
    const float* __restrict__ bias, float* __restrict__ out)
{
    __shared__ float ins[2][34][36];
    __shared__ float wsc[96];
    const int tid = threadIdx.x;
    const int b = blockIdx.y;
    const int tileY = (blockIdx.x >> 1) << 5;
    const int tileX = (blockIdx.x & 1) << 5;
    const int lmy = (tid >> 4) << 1;
    const int lmx = (tid & 15) << 1;

    float acc[48];
#pragma unroll
    for (int i = 0; i < 48; i++) acc[i] = 0.f;

    const float* inb = in + (size_t)b * 256 * 4096;

    for (int c0 = 0; c0 < 256; c0 += 2) {
        __syncthreads();
        for (int e = tid; e < 2 * 34 * 34; e += 256) {
            int cc = (e >= 1156) ? 1 : 0;
            int rem = e - cc * 1156;
            int r = rem / 34, c = rem - r * 34;
            int gy = tileY - 1 + r, gx = tileX - 1 + c;
            float v = 0.f;
            if ((unsigned)gy < 64u && (unsigned)gx < 64u)
                v = inb[(c0 + cc) * 4096 + (gy << 6) + gx];
            ins[cc][r][c] = v;
        }
        if (tid < 96) wsc[tid] = wpk[c0 * 48 + tid];
        __syncthreads();
#pragma unroll
        for (int cc = 0; cc < 2; cc++) {
            float r4[4][4];
#pragma unroll
            for (int dy = 0; dy < 4; dy++)
#pragma unroll
                for (int dx = 0; dx < 4; dx++)
                    r4[dy][dx] = ins[cc][lmy + dy][lmx + dx];
#pragma unroll
            for (int co = 0; co < 3; co++)
#pragma unroll
                for (int par = 0; par < 4; par++) {
                    int ry = par >> 1, rx = par & 1;
                    float4 w = *(const float4*)&wsc[cc * 48 + co * 16 + par * 4];
#pragma unroll
                    for (int dmy = 0; dmy < 2; dmy++)
#pragma unroll
                        for (int dmx = 0; dmx < 2; dmx++) {
                            acc[((dmy * 2 + dmx) * 3 + co) * 4 + par] +=
                                  w.x * r4[dmy + ry][dmx + rx]
                                + w.y * r4[dmy + ry][dmx + 1 + rx]
                                + w.z * r4[dmy + 1 + ry][dmx + rx]
                                + w.w * r4[dmy + 1 + ry][dmx + 1 + rx];
                        }
                }
        }
    }

#pragma unroll
    for (int dmy = 0; dmy < 2; dmy++)
#pragma unroll
        for (int dmx = 0; dmx < 2; dmx++)
#pragma unroll
            for (int co = 0; co < 3; co++)
#pragma unroll
                for (int par = 0; par < 4; par++) {
                    int ry = par >> 1, rx = par & 1;
                    int my = tileY + lmy + dmy, mx = tileX + lmx + dmx;
                    int oy = (my << 1) + ry, ox = (mx << 1) + rx;
                    float v = acc[((dmy * 2 + dmx) * 3 + co) * 4 + par] + bias[co];
                    v = 1.f / (1.f + expf(-v));
                    out[((b * 3 + co) << 14) + (oy << 7) + ox] = v;
                }
}

// ---------------------------------------------------------------------------
// launcher
// ---------------------------------------------------------------------------
extern "C" void kernel_launch(void* const* d_in, const int* in_sizes, int n_in,
                              void* d_out, int out_size)
{
    const float* x     = (const float*)d_in[0];
    const float* embed = (const float*)d_in[1];
    const float* dt1_b = (const float*)d_in[13];
    const float* dt2_b = (const float*)d_in[15];
    float* out = (float*)d_out;

    __nv_bfloat16 *colh, *wtsh;
    float *h1, *h2, *tb, *ab, *ze, *zq, *bb, *S, *d1, *enrm, *wpk, *part;
    int* idxp;
    cudaGetSymbolAddress((void**)&colh, g_colh);
    cudaGetSymbolAddress((void**)&wtsh, g_wtsh);
    cudaGetSymbolAddress((void**)&h1,   g_h1);
    cudaGetSymbolAddress((void**)&h2,   g_h2);
    cudaGetSymbolAddress((void**)&tb,   g_t);
    cudaGetSymbolAddress((void**)&ab,   g_a);
    cudaGetSymbolAddress((void**)&ze,   g_ze);
    cudaGetSymbolAddress((void**)&zq,   g_zq);
    cudaGetSymbolAddress((void**)&bb,   g_b2);
    cudaGetSymbolAddress((void**)&S,    g_s);
    cudaGetSymbolAddress((void**)&d1,   g_d1);
    cudaGetSymbolAddress((void**)&enrm, g_enorm);
    cudaGetSymbolAddress((void**)&wpk,  g_wpk);
    cudaGetSymbolAddress((void**)&part, g_part);
    cudaGetSymbolAddress((void**)&idxp, g_idx);

    cudaFuncSetAttribute(gemm_bf16x, cudaFuncAttributeMaxDynamicSharedMemorySize, GEMM_SMEM_H);

    // ---- weight prep: single launch ----
    PrepArgs pa;
    pa.w[0]  = (const float*)d_in[2];   // e_w1
    pa.w[1]  = (const float*)d_in[3];   // e_w2
    pa.w[2]  = (const float*)d_in[4];   // e_r1a
    pa.w[3]  = (const float*)d_in[5];   // e_r1b
    pa.w[4]  = (const float*)d_in[6];   // e_r2a
    pa.w[5]  = (const float*)d_in[7];   // e_r2b
    pa.w[6]  = (const float*)d_in[8];   // d_r1a
    pa.w[7]  = (const float*)d_in[9];   // d_r1b
    pa.w[8]  = (const float*)d_in[10];  // d_r2a
    pa.w[9]  = (const float*)d_in[11];  // d_r2b
    pa.w[10] = embed;
    pa.dt1   = (const float*)d_in[12];
    pa.dt2   = (const float*)d_in[14];
    prep_weights<<<dim3(4096, 16), 256>>>(pa, wtsh, wpk);

    // ---- encoder conv1: 3 -> 256, k4 s2 p1, 128 -> 64, relu (K_pad=64), full ----
    im2colT_conv_h<<<dim3(N_HALF / 32, 2), 256>>>(x, colh, (size_t)N_HALF * 64, 3,
        3, 128, 128, 12, 6, 16, 4, 2, 1, 48, 64);
    gemm_bf16x<<<dim3(2, N_HALF / 128), 256, GEMM_SMEM_H>>>(
        wtsh + OFF_C1, WPLANE, colh, (size_t)N_HALF * 64, h1, 256, 64, 1,
        12, 6, 64, 64, 1, 1, 0, 0, nullptr, nullptr, 1);

    // ---- encoder conv2: 256 -> 256, k4 s2 p1, 64 -> 32, relu, 2-plane ----
    im2colT_conv_h<<<dim3(N_LAT / 32, 128), 256>>>(h1, colh, (size_t)N_LAT * 4096, 2,
        256, 64, 64, 10, 5, 16, 4, 2, 1, 4096, 4096);
    gemm_bf16x<<<dim3(2, N_LAT / 128), 256, GEMM_SMEM_H>>>(
        wtsh + OFF_C2, WPLANE, colh, (size_t)N_LAT * 4096, h2, 256, 4096, 0,
        10, 5, 32, 32, 1, 1, 0, 0, nullptr, nullptr, 1);

    // ---- residual block: 3x3 relu -> 1x1 + residual (2-plane) ----
    auto res = [&](const float* src, int offA, int offB, float* tmp, float* dst) {
        im2colT_conv_h<<<dim3(N_LAT / 32, 72), 256>>>(src, colh, (size_t)N_LAT * 2304, 2,
            256, 32, 32, 10, 5, 9, 3, 1, 1, 2304, 2304);
        gemm_bf16x<<<dim3(2, N_LAT / 128), 256, GEMM_SMEM_H>>>(
            wtsh + offA, WPLANE, colh, (size_t)N_LAT * 2304, tmp, 256, 2304, 0,
            10, 5, 32, 32, 1, 1, 0, 0, nullptr, nullptr, 1);
        im2colT_conv_h<<<dim3(N_LAT / 32, 8), 256>>>(tmp, colh, (size_t)N_LAT * 256, 2,
            256, 32, 32, 10, 5, 1, 1, 1, 0, 256, 256);
        gemm_bf16x<<<dim3(2, N_LAT / 128), 256, GEMM_SMEM_H>>>(
            wtsh + offB, WPLANE, colh, (size_t)N_LAT * 256, dst, 256, 256, 0,
            10, 5, 32, 32, 1, 1, 0, 0, nullptr, src, 0);
    };
    res(h2, OFF_ER1A, OFF_ER1B, tb, ab);
    res(ab, OFF_ER2A, OFF_ER2B, tb, ze);

    // ---- vector quantisation (full-precision scores) ----
    im2colT_conv_h<<<dim3(N_LAT / 32, 8), 256>>>(ze, colh, (size_t)N_LAT * 256, 3,
        256, 32, 32, 10, 5, 1, 1, 1, 0, 256, 256);
    vq_enorm<<<512, 256>>>(embed, enrm);
    gemm_bf16x<<<dim3(4, N_LAT / 128), 256, GEMM_SMEM_H>>>(
        wtsh + OFF_EMB, WPLANE, colh, (size_t)N_LAT * 256, S, 512, 256, 1,
        15, 15, 1, N_LAT, 1, 1, 0, 0, nullptr, nullptr, 0);
    vq_argmin<<<N_LAT / 256, 256>>>(S, enrm, idxp);
    vq_gather<<<1024, 256>>>(ze, embed, idxp, zq, part);

    // ---- decoder residual blocks ----
    res(zq, OFF_DR1A, OFF_DR1B, tb, ab);
    res(ab, OFF_DR2A, OFF_DR2B, tb, bb);

    // ---- deconv1: 256 -> 256, k4 s2 p1, 32 -> 64, +bias, relu (4 parity GEMMs) ----
    for (int par = 0; par < 4; par++) {
        int ry = par >> 1, rx = par & 1;
        im2colT_dec_h<<<dim3(N_LAT / 32, 32), 256>>>(bb, colh, (size_t)N_LAT * 1024, ry, rx);
        gemm_bf16x<<<dim3(2, N_LAT / 128), 256, GEMM_SMEM_H>>>(
            wtsh + OFF_DT1 + par * 262144, WPLANE, colh, (size_t)N_LAT * 1024, d1, 256, 1024, 0,
            10, 5, 64, 64, 2, 2, ry, rx, dt1_b, nullptr, 1);
    }

    // ---- deconv2: 256 -> 3, k4 s2 p1, 64 -> 128, +bias, sigmoid ----
    deconv2_sig<<<dim3(4, 32), 256>>>(d1, wpk, dt2_b, out);

    // ---- losses ----
    loss_write<<<1, 256>>>(part, out, out_size);
}

// round 15
// speedup vs baseline: 1.7409x; 1.2768x over previous
#include <cuda_runtime.h>
#include <cuda_bf16.h>
#include <math.h>
#include <stdint.h>

// ---------------------------------------------------------------------------
// VQ-VAE forward — implicit bf16-split mma.sync GEMM over NHWC activations.
// 2-plane/3-product bulk; 3-plane/6-product conv1 + VQ scores.
// B=32, CIN=3, IMG=128, D=256, K=512. Latent 32x32.
// ---------------------------------------------------------------------------

#define N_LAT 32768      // B * 32 * 32
#define N_HALF 131072    // B * 64 * 64
#define WPLANE 5242880   // weight plane stride (elements)

// ---- scratch (device globals; allocation is forbidden) ----
static __device__ __nv_bfloat16 g_colh[402653184]; // bf16 activation arena
static __device__ __nv_bfloat16 g_wtsh[15728640];  // 3 planes x 5242880
static __device__ float g_h2[8388608];     // h2 fp32 NHWC
static __device__ float g_a[8388608];      // ab fp32 NHWC
static __device__ float g_ze[8388608];     // ze fp32 NHWC
static __device__ float g_zq[8388608];     // zq fp32 NHWC
static __device__ float g_b2[8388608];     // bb fp32 NHWC
static __device__ float g_s[16777216];     // (512, 32768) VQ scores
static __device__ float g_d1[33554432];    // (32,256,64,64) deconv1 out NCHW
static __device__ int   g_idx[32768];
static __device__ float g_enorm[512];
static __device__ float g_wpk[12288];      // deconv2 repacked weights (fp32)
static __device__ float g_part[4096];      // loss partials

// activation offsets in g_colh (elements)
#define H1H   0           // 2 planes, ps 33554432 (NHWC 64x64x256)
#define H2H   67108864    // 2 planes, ps 8388608 (NHWC 32x32x256)
#define TMPH  83886080
#define ABH   100663296
#define ZEH   117440512   // 3 planes
#define ZQH   142606336
#define BBH   159383552
#define COLA  201326592   // conv1 col [n][64], 3 planes, ps 8388608
#define PS_LAT 8388608
#define PS_H1  33554432

// weight offsets within one plane (elements)
#define OFF_C1    0          // 256 x 64
#define OFF_C2    16384      // 256 x 4096 (rs-major)
#define OFF_ER1A  1064960    // 256 x 2304 (rs-major)
#define OFF_ER1B  1654784    // 256 x 256
#define OFF_ER2A  1720320
#define OFF_ER2B  2310144
#define OFF_DR1A  2375680
#define OFF_DR1B  2965504
#define OFF_DR2A  3031040
#define OFF_DR2B  3620864
#define OFF_EMB   3686400    // 512 x 256
#define OFF_DT1   3817472    // 4 x (256 x 1024) tap-major

// ---------------------------------------------------------------------------
// helpers
// ---------------------------------------------------------------------------
__device__ __forceinline__ uint32_t smem_u32(const void* p) {
    uint32_t a;
    asm("{ .reg .u64 t; cvta.to.shared.u64 t, %1; cvt.u32.u64 %0, t; }" : "=r"(a) : "l"(p));
    return a;
}

__device__ __forceinline__ void cp16(uint32_t dst, const void* src) {
    asm volatile("cp.async.cg.shared.global [%0], [%1], 16;" :: "r"(dst), "l"(src));
}

__device__ __forceinline__ void cp16z(uint32_t dst, const void* src, int sz) {
    asm volatile("cp.async.cg.shared.global [%0], [%1], 16, %2;"
                 :: "r"(dst), "l"(src), "r"(sz));
}

__device__ __forceinline__ uint32_t lds32(uint32_t a) {
    uint32_t v;
    asm volatile("ld.shared.b32 %0, [%1];" : "=r"(v) : "r"(a));
    return v;
}

__device__ __forceinline__ void mma16(float* d, const uint32_t* a, const uint32_t* b) {
    asm volatile(
        "mma.sync.aligned.m16n8k16.row.col.f32.bf16.bf16.f32 "
        "{%0,%1,%2,%3}, {%4,%5,%6,%7}, {%8,%9}, {%0,%1,%2,%3};"
        : "+f"(d[0]), "+f"(d[1]), "+f"(d[2]), "+f"(d[3])
        : "r"(a[0]), "r"(a[1]), "r"(a[2]), "r"(a[3]), "r"(b[0]), "r"(b[1]));
}

__device__ __forceinline__ void split3(float v, uint16_t& q0, uint16_t& q1, uint16_t& q2) {
    __nv_bfloat16 h0 = __float2bfloat16(v);
    float r1 = v - __bfloat162float(h0);
    __nv_bfloat16 h1 = __float2bfloat16(r1);
    float r2 = r1 - __bfloat162float(h1);
    __nv_bfloat16 h2 = __float2bfloat16(r2);
    q0 = __bfloat16_as_ushort(h0);
    q1 = __bfloat16_as_ushort(h1);
    q2 = __bfloat16_as_ushort(h2);
}

__device__ __forceinline__ void split2(float v, uint16_t& q0, uint16_t& q1) {
    __nv_bfloat16 h0 = __float2bfloat16(v);
    float r1 = v - __bfloat162float(h0);
    __nv_bfloat16 h1 = __float2bfloat16(r1);
    q0 = __bfloat16_as_ushort(h0);
    q1 = __bfloat16_as_ushort(h1);
}

__device__ __forceinline__ uint32_t pack2(uint16_t lo, uint16_t hi) {
    return (uint32_t)lo | ((uint32_t)hi << 16);
}

// ---------------------------------------------------------------------------
// Implicit bf16x GEMM:  C[m][n] = sum_k A[m][k] * B_im2col[n][k]
//   A: weight planes, K reordered rs-major (k = rs*Cin + ci).
//   B: NHWC bf16 activation planes; loader computes tap address per k-chunk,
//      OOB rows zero-filled via cp.async src-size 0.
//   full=1: 3 planes / 6 products; full=0: 2 planes / 3 products.
//   CTA 128(M) x 128(N pixels), 8 warps, k-step 32, 3-stage cp.async.
//   epi=0: NHWC out (bf16 planes [+fp32], resid/relu);
//   epi=1: NCHW scatter fp32 (bias/relu) — also VQ rowmajor via params.
// ---------------------------------------------------------------------------
#define GEMM_SMEM_H 184320   // 3 stages * 6 plane slots * 128 rows * 80 B

__global__ void __launch_bounds__(256, 1) gemm_imp(
    const __nv_bfloat16* __restrict__ A3, size_t aStride,
    const __nv_bfloat16* __restrict__ Bb, size_t bStride,
    int M, int K_pad, int full,
    int Cin, int logCPR, int S_t, int oy0, int ox0, int strideIn,
    int Hin, int Win, int logHWo, int logWo,
    int epi, __nv_bfloat16* __restrict__ Dh, size_t dhStride, int dhPlanes,
    float* __restrict__ Df, const float* __restrict__ residf,
    const float* __restrict__ bias, int relu,
    int Hout, int Wout, int sy, int sx, int ry, int rx)
{
    extern __shared__ char smc[];
    const int tid = threadIdx.x;
    const int lane = tid & 31, warp = tid >> 5;
    const int g = lane >> 2, t = lane & 3;
    const int wm = (warp >> 2) << 6;   // 0/64
    const int wn = (warp & 3) << 5;    // 0..96
    const int bm = blockIdx.x << 7;    // M-tile
    const int bn = blockIdx.y << 7;    // pixel tile
    const uint32_t sb = smem_u32(smc);
    const int nk = K_pad >> 5;
    const int np = full ? 3 : 2;
    const int hwmask = (1 << logHWo) - 1;
    const int wmask = (1 << logWo) - 1;

    float acc[4][4][4];
#pragma unroll
    for (int i = 0; i < 4; i++)
#pragma unroll
        for (int j = 0; j < 4; j++)
#pragma unroll
            for (int q = 0; q < 4; q++) acc[i][j][q] = 0.f;

    auto loadStage = [&](int it, int slot) {
        const uint32_t st = sb + slot * 61440;
        const int k0 = it << 5;
        const int rs = it >> logCPR;
        const int ci0 = (it & ((1 << logCPR) - 1)) << 5;
        const int dy = rs / S_t + oy0;
        const int dx = rs % S_t + ox0;
        const int groups = full ? 12 : 8;
#pragma unroll
        for (int j = 0; j < 12; j++) {
            if (j >= groups) break;
            int c = j * 256 + tid;
            int pg0 = c >> 9;
            int pg = full ? pg0 : ((pg0 & 1) + ((pg0 >> 1) * 3));  // 0,1,3,4
            int r  = (c >> 2) & 127;
            int u  = c & 3;
            uint32_t dst = st + pg * 10240 + r * 80 + u * 16;
            if (pg < 3) {
                cp16(dst, A3 + (size_t)pg * aStride + (size_t)(bm + r) * K_pad + k0 + u * 8);
            } else {
                int n = bn + r;
                int b = n >> logHWo;
                int pp = n & hwmask;
                int oy = pp >> logWo, ox = pp & wmask;
                int iy = oy * strideIn + dy, ix = ox * strideIn + dx;
                bool valid = ((unsigned)iy < (unsigned)Hin) && ((unsigned)ix < (unsigned)Win);
                const __nv_bfloat16* src = Bb + (size_t)(pg - 3) * bStride
                    + (size_t)((b * Hin + iy) * Win + ix) * Cin + ci0 + u * 8;
                if (!valid) src = Bb;
                cp16z(dst, src, valid ? 16 : 0);
            }
        }
        asm volatile("cp.async.commit_group;");
    };

    loadStage(0, 0);
    if (nk > 1) loadStage(1, 1);

    for (int it = 0; it < nk; it++) {
        if (it <= nk - 2) asm volatile("cp.async.wait_group 1;");
        else              asm volatile("cp.async.wait_group 0;");
        __syncthreads();
        if (it + 2 < nk) loadStage(it + 2, (it + 2) % 3);

        const uint32_t st = sb + (it % 3) * 61440;
#pragma unroll
        for (int h = 0; h < 2; h++) {
            uint32_t bf[4][3][2];
#pragma unroll
            for (int nt = 0; nt < 4; nt++)
#pragma unroll
                for (int p = 0; p < 3; p++) {
                    if (p >= np) break;
                    uint32_t ad = st + 30720 + p * 10240
                                + (wn + (nt << 3) + g) * 80 + (h << 5) + (t << 2);
                    bf[nt][p][0] = lds32(ad);
                    bf[nt][p][1] = lds32(ad + 16);
                }
#pragma unroll
            for (int mt = 0; mt < 4; mt++) {
                uint32_t af[3][4];
#pragma unroll
                for (int p = 0; p < 3; p++) {
                    if (p >= np) break;
                    uint32_t ad = st + p * 10240
                                + (wm + (mt << 4) + g) * 80 + (h << 5) + (t << 2);
                    af[p][0] = lds32(ad);
                    af[p][1] = lds32(ad + 640);
                    af[p][2] = lds32(ad + 16);
                    af[p][3] = lds32(ad + 656);
                }
#pragma unroll
                for (int nt = 0; nt < 4; nt++) mma16(acc[mt][nt], af[0], bf[nt][0]);
#pragma unroll
                for (int nt = 0; nt < 4; nt++) mma16(acc[mt][nt], af[1], bf[nt][0]);
#pragma unroll
                for (int nt = 0; nt < 4; nt++) mma16(acc[mt][nt], af[0], bf[nt][1]);
                if (full) {
#pragma unroll
                    for (int nt = 0; nt < 4; nt++) mma16(acc[mt][nt], af[1], bf[nt][1]);
#pragma unroll
                    for (int nt = 0; nt < 4; nt++) mma16(acc[mt][nt], af[2], bf[nt][0]);
#pragma unroll
                    for (int nt = 0; nt < 4; nt++) mma16(acc[mt][nt], af[0], bf[nt][2]);
                }
            }
        }
    }

    if (epi == 0) {
        // ---- NHWC epilogue: split planes (+ optional fp32), resid/relu ----
#pragma unroll
        for (int mt = 0; mt < 4; mt++)
#pragma unroll
            for (int half = 0; half < 2; half++) {
                int m = bm + wm + (mt << 4) + g + (half << 3);
#pragma unroll
                for (int nt = 0; nt < 4; nt++)
#pragma unroll
                    for (int j = 0; j < 2; j++) {
                        int n = bn + wn + (nt << 3) + (t << 1) + j;
                        float v = acc[mt][nt][half * 2 + j];
                        size_t o = (size_t)n * M + m;
                        if (residf) v += residf[o];
                        if (relu) v = fmaxf(v, 0.f);
                        if (Df) Df[o] = v;
                        if (dhPlanes == 3) {
                            uint16_t q0, q1, q2;
                            split3(v, q0, q1, q2);
                            Dh[o] = __ushort_as_bfloat16(q0);
                            Dh[dhStride + o] = __ushort_as_bfloat16(q1);
                            Dh[2 * dhStride + o] = __ushort_as_bfloat16(q2);
                        } else {
                            uint16_t q0, q1;
                            split2(v, q0, q1);
                            Dh[o] = __ushort_as_bfloat16(q0);
                            Dh[dhStride + o] = __ushort_as_bfloat16(q1);
                        }
                    }
            }
    } else {
        // ---- NCHW parity scatter (deconv1) / rowmajor (VQ) ----
        const int HWout = Hout * Wout;
#pragma unroll
        for (int mt = 0; mt < 4; mt++)
#pragma unroll
            for (int half = 0; half < 2; half++) {
                int m = bm + wm + (mt << 4) + g + (half << 3);
                float bv = bias ? bias[m] : 0.f;
                int mb = m * HWout;
#pragma unroll
                for (int nt = 0; nt < 4; nt++) {
                    int n = bn + wn + (nt << 3) + (t << 1);
                    int bimg = n >> logHWo;
                    int p = n & hwmask;
                    int yy = p >> logWo, xx = p & wmask;
                    int o = bimg * M * HWout + mb + (yy * sy + ry) * Wout + xx * sx + rx;
                    float v0 = acc[mt][nt][half * 2 + 0] + bv;
                    float v1 = acc[mt][nt][half * 2 + 1] + bv;
                    if (relu) { v0 = fmaxf(v0, 0.f); v1 = fmaxf(v1, 0.f); }
                    Df[o] = v0;
                    Df[o + sx] = v1;
                }
            }
    }
}

// ---------------------------------------------------------------------------
// conv1 im2col: x (NCHW fp32, C=3) -> col [n][64] 3-plane bf16 (k = ci*16+rs)
// ---------------------------------------------------------------------------
__global__ void im2colT_conv_h(const float* __restrict__ in, __nv_bfloat16* __restrict__ colh,
                               size_t planeStride,
                               int C, int Hin, int Win, int logHW, int logW,
                               int RS, int S, int stride, int pad, int K, int K_pad)
{
    __shared__ float s[32][33];
    const int tid = threadIdx.x;
    const int n0 = blockIdx.x << 5, k0 = blockIdx.y << 5;
    const int nl = tid & 31, kr = tid >> 5;
    const int n = n0 + nl;
    const int b = n >> logHW;
    const int p = n & ((1 << logHW) - 1);
    const int oy = p >> logW, ox = p & ((1 << logW) - 1);
#pragma unroll
    for (int pass = 0; pass < 4; pass++) {
        int k = k0 + pass * 8 + kr;
        float v = 0.f;
        if (k < K) {
            int ci = k / RS;
            int rs = k - ci * RS;
            int r = rs / S, ss = rs - r * S;
            int iy = oy * stride - pad + r;
            int ix = ox * stride - pad + ss;
            if ((unsigned)iy < (unsigned)Hin && (unsigned)ix < (unsigned)Win)
                v = in[((b * C + ci) * Hin + iy) * Win + ix];
        }
        s[pass * 8 + kr][nl] = v;
    }
    __syncthreads();
    const int onl = tid >> 3, kq = tid & 7;
    uint16_t q0[4], q1[4], q2[4];
#pragma unroll
    for (int j = 0; j < 4; j++) split3(s[kq * 4 + j][onl], q0[j], q1[j], q2[j]);
    size_t base = (size_t)(n0 + onl) * K_pad + k0 + kq * 4;
    *(uint2*)(colh + base)                   = make_uint2(pack2(q0[0], q0[1]), pack2(q0[2], q0[3]));
    *(uint2*)(colh + planeStride + base)     = make_uint2(pack2(q1[0], q1[1]), pack2(q1[2], q1[3]));
    *(uint2*)(colh + 2 * planeStride + base) = make_uint2(pack2(q2[0], q2[1]), pack2(q2[2], q2[3]));
}

// ---------------------------------------------------------------------------
// unified weight prep (single launch). Conv layers reordered rs-major.
// ---------------------------------------------------------------------------
struct PrepArgs {
    const float* w[11];
    const float* dt1;
    const float* dt2;
};

__global__ void prep_weights(PrepArgs pa, __nv_bfloat16* __restrict__ wtsh,
                             float* __restrict__ wpk)
{
    const int y = blockIdx.y;
    const int i = blockIdx.x * 256 + threadIdx.x;
    if (y < 11) {
        const int Ks[11] = {48, 4096, 2304, 256, 2304, 256, 2304, 256, 2304, 256, 256};
        const int Kp[11] = {64, 4096, 2304, 256, 2304, 256, 2304, 256, 2304, 256, 256};
        const int Ms[11] = {256, 256, 256, 256, 256, 256, 256, 256, 256, 256, 512};
        const int RSs[11] = {0, 16, 9, 0, 9, 0, 9, 0, 9, 0, 0};  // 0 = direct
        const int Of[11] = {OFF_C1, OFF_C2, OFF_ER1A, OFF_ER1B, OFF_ER2A, OFF_ER2B,
                            OFF_DR1A, OFF_DR1B, OFF_DR2A, OFF_DR2B, OFF_EMB};
        int K = Ks[y], K_pad = Kp[y], M = Ms[y], RS = RSs[y], off = Of[y];
        if (i >= M * K_pad) return;
        int m = i / K_pad, k = i - m * K_pad;
        float v;
        if (RS > 0) {
            int ci = k & 255, rs = k >> 8;
            v = pa.w[y][m * K + ci * RS + rs];
        } else {
            v = (k < K) ? pa.w[y][m * K + k] : 0.f;
        }
        uint16_t q0, q1, q2;
        split3(v, q0, q1, q2);
        wtsh[off + i] = __ushort_as_bfloat16(q0);
        wtsh[WPLANE + off + i] = __ushort_as_bfloat16(q1);
        wtsh[2 * WPLANE + off + i] = __ushort_as_bfloat16(q2);
    } else if (y < 15) {
        if (i >= 262144) return;
        int par = y - 11;
        int ry = par >> 1, rx = par & 1;
        int co = i >> 10;
        int k = i & 1023;
        int ci = k & 255, tap = k >> 8;      // tap-major
        int a = tap >> 1, bb = tap & 1;
        float v = pa.dt1[((ci * 256 + co) * 4 + (3 - ry - 2 * a)) * 4 + (3 - rx - 2 * bb)];
        uint16_t q0, q1, q2;
        split3(v, q0, q1, q2);
        int off = OFF_DT1 + par * 262144;
        wtsh[off + i] = __ushort_as_bfloat16(q0);
        wtsh[WPLANE + off + i] = __ushort_as_bfloat16(q1);
        wtsh[2 * WPLANE + off + i] = __ushort_as_bfloat16(q2);
    } else {
        if (i >= 12288) return;
        int tap = i & 3;
        int par = (i >> 2) & 3;
        int co = (i >> 4) % 3;
        int ci = i / 48;
        int a = tap >> 1, bb = tap & 1;
        int ry = par >> 1, rx = par & 1;
        wpk[i] = pa.dt2[((ci * 3 + co) * 4 + (3 - ry - 2 * a)) * 4 + (3 - rx - 2 * bb)];
    }
}

// ---------------------------------------------------------------------------
// VQ kernels
// ---------------------------------------------------------------------------
__global__ void vq_enorm(const float* __restrict__ e, float* __restrict__ en)
{
    __shared__ float s[256];
    int k = blockIdx.x;
    float v = e[k * 256 + threadIdx.x];
    s[threadIdx.x] = v * v;
    __syncthreads();
    for (int off = 128; off > 0; off >>= 1) {
        if (threadIdx.x < off) s[threadIdx.x] += s[threadIdx.x + off];
        __syncthreads();
    }
    if (threadIdx.x == 0) en[k] = s[0];
}

__global__ void vq_argmin(const float* __restrict__ S, const float* __restrict__ en,
                          int* __restrict__ idx)
{
    int n = blockIdx.x * 256 + threadIdx.x;
    if (n >= N_LAT) return;
    float best = 3.4e38f;
    int bi = 0;
    for (int k = 0; k < 512; k++) {
        float v = en[k] - 2.f * S[k * N_LAT + n];
        if (v < best) { best = v; bi = k; }
    }
    idx[n] = bi;
}

// gather z_q: NHWC fp32 + 2-plane NHWC bf16, deterministic loss partials
__global__ void vq_gather(const float* __restrict__ zef, const float* __restrict__ embed,
                          const int* __restrict__ idx, float* __restrict__ zqf,
                          __nv_bfloat16* __restrict__ zqh, size_t ps,
                          float* __restrict__ part)
{
    __shared__ float s[8];
    int warp = threadIdx.x >> 5, lane = threadIdx.x & 31;
    int n = blockIdx.x * 8 + warp;
    int id = idx[n];
    float acc = 0.f;
    for (int d = lane; d < 256; d += 32) {
        float e = embed[id * 256 + d];
        float z = zef[(size_t)n * 256 + d];
        zqf[(size_t)n * 256 + d] = e;
        uint16_t q0, q1;
        split2(e, q0, q1);
        zqh[(size_t)n * 256 + d] = __ushort_as_bfloat16(q0);
        zqh[ps + (size_t)n * 256 + d] = __ushort_as_bfloat16(q1);
        float df = z - e;
        acc += df * df;
    }
#pragma unroll
    for (int off = 16; off > 0; off >>= 1)
        acc += __shfl_xor_sync(0xffffffffu, acc, off);
    if (lane == 0) s[warp] = acc;
    __syncthreads();
    if (threadIdx.x == 0) {
        float v = 0.f;
        for (int w = 0; w < 8; w++) v += s[w];
        part[blockIdx.x] = v;
    }
}

__global__ void loss_write(const float* __restrict__ part, float* __restrict__ out, int out_size)
{
    __shared__ float s[256];
    float v = 0.f;
    for (int i = threadIdx.x; i < 4096; i += 256) v += part[i];
    s[threadIdx.x] = v;
    __syncthreads();
    for (int off = 128; off > 0; off >>= 1) {
        if (threadIdx.x < off) s[threadIdx.x] += s[threadIdx.x + off];
        __syncthreads();
    }
    if (threadIdx.x == 0 && out_size >= 2) {
        float L = s[0] / 32768.f;
        out[out_size - 2] = L;
        out[out_size - 1] = L;
    }
}

// ---------------------------------------------------------------------------
// deconv2 (256 -> 3, k4 s2 p1) + sigmoid, direct parity kernel (d1 NCHW fp32).
// ---------------------------------------------------------------------------
__global__ __launch_bounds__(256) void deconv2_sig(
    const float* __restrict__ in, const float* __restrict__ wpk,
    const float* __restrict__ bias, float* __restrict__ out)
{
    __shared__ float ins[2][34][36];
    __shared__ float wsc[96];
    const int tid = threadIdx.x;
    const int b = blockIdx.y;
    const int tileY = (blockIdx.x >> 1) << 5;
    const int tileX = (blockIdx.x & 1) << 5;
    const int lmy = (tid >> 4) << 1;
    const int lmx = (tid & 15) << 1;

    float acc[48];
#pragma unroll
    for (int i = 0; i < 48; i++) acc[i] = 0.f;

    const float* inb = in + (size_t)b * 256 * 4096;

    for (int c0 = 0; c0 < 256; c0 += 2) {
        __syncthreads();
        for (int e = tid; e < 2 * 34 * 34; e += 256) {
            int cc = (e >= 1156) ? 1 : 0;
            int rem = e - cc * 1156;
            int r = rem / 34, c = rem - r * 34;
            int gy = tileY - 1 + r, gx = tileX - 1 + c;
            float v = 0.f;
            if ((unsigned)gy < 64u && (unsigned)gx < 64u)
                v = inb[(c0 + cc) * 4096 + (gy << 6) + gx];
            ins[cc][r][c] = v;
        }
        if (tid < 96) wsc[tid] = wpk[c0 * 48 + tid];
        __syncthreads();
#pragma unroll
        for (int cc = 0; cc < 2; cc++) {
            float r4[4][4];
#pragma unroll
            for (int dy = 0; dy < 4; dy++)
#pragma unroll
                for (int dx = 0; dx < 4; dx++)
                    r4[dy][dx] = ins[cc][lmy + dy][lmx + dx];
#pragma unroll
            for (int co = 0; co < 3; co++)
#pragma unroll
                for (int par = 0; par < 4; par++) {
                    int ry = par >> 1, rx = par & 1;
                    float4 w = *(const float4*)&wsc[cc * 48 + co * 16 + par * 4];
#pragma unroll
                    for (int dmy = 0; dmy < 2; dmy++)
#pragma unroll
                        for (int dmx = 0; dmx < 2; dmx++) {
                            acc[((dmy * 2 + dmx) * 3 + co) * 4 + par] +=
                                  w.x * r4[dmy + ry][dmx + rx]
                                + w.y * r4[dmy + ry][dmx + 1 + rx]
                                + w.z * r4[dmy + 1 + ry][dmx + rx]
                                + w.w * r4[dmy + 1 + ry][dmx + 1 + rx];
                        }
                }
        }
    }

#pragma unroll
    for (int dmy = 0; dmy < 2; dmy++)
#pragma unroll
        for (int dmx = 0; dmx < 2; dmx++)
#pragma unroll
            for (int co = 0; co < 3; co++)
#pragma unroll
                for (int par = 0; par < 4; par++) {
                    int ry = par >> 1, rx = par & 1;
                    int my = tileY + lmy + dmy, mx = tileX + lmx + dmx;
                    int oy = (my << 1) + ry, ox = (mx << 1) + rx;
                    float v = acc[((dmy * 2 + dmx) * 3 + co) * 4 + par] + bias[co];
                    v = 1.f / (1.f + expf(-v));
                    out[((b * 3 + co) << 14) + (oy << 7) + ox] = v;
                }
}

// ---------------------------------------------------------------------------
// launcher
// ---------------------------------------------------------------------------
extern "C" void kernel_launch(void* const* d_in, const int* in_sizes, int n_in,
                              void* d_out, int out_size)
{
    const float* x     = (const float*)d_in[0];
    const float* embed = (const float*)d_in[1];
    const float* dt1_b = (const float*)d_in[13];
    const float* dt2_b = (const float*)d_in[15];
    float* out = (float*)d_out;

    __nv_bfloat16 *colh, *wtsh;
    float *h2f, *abf, *zef, *zqf, *bbf, *S, *d1, *enrm, *wpk, *part;
    int* idxp;
    cudaGetSymbolAddress((void**)&colh, g_colh);
    cudaGetSymbolAddress((void**)&wtsh, g_wtsh);
    cudaGetSymbolAddress((void**)&h2f,  g_h2);
    cudaGetSymbolAddress((void**)&abf,  g_a);
    cudaGetSymbolAddress((void**)&zef,  g_ze);
    cudaGetSymbolAddress((void**)&zqf,  g_zq);
    cudaGetSymbolAddress((void**)&bbf,  g_b2);
    cudaGetSymbolAddress((void**)&S,    g_s);
    cudaGetSymbolAddress((void**)&d1,   g_d1);
    cudaGetSymbolAddress((void**)&enrm, g_enorm);
    cudaGetSymbolAddress((void**)&wpk,  g_wpk);
    cudaGetSymbolAddress((void**)&part, g_part);
    cudaGetSymbolAddress((void**)&idxp, g_idx);

    cudaFuncSetAttribute(gemm_imp, cudaFuncAttributeMaxDynamicSharedMemorySize, GEMM_SMEM_H);

    // ---- weight prep ----
    PrepArgs pa;
    pa.w[0]  = (const float*)d_in[2];
    pa.w[1]  = (const float*)d_in[3];
    pa.w[2]  = (const float*)d_in[4];
    pa.w[3]  = (const float*)d_in[5];
    pa.w[4]  = (const float*)d_in[6];
    pa.w[5]  = (const float*)d_in[7];
    pa.w[6]  = (const float*)d_in[8];
    pa.w[7]  = (const float*)d_in[9];
    pa.w[8]  = (const float*)d_in[10];
    pa.w[9]  = (const float*)d_in[11];
    pa.w[10] = embed;
    pa.dt1   = (const float*)d_in[12];
    pa.dt2   = (const float*)d_in[14];
    prep_weights<<<dim3(4096, 16), 256>>>(pa, wtsh, wpk);

    // ---- conv1: im2col (C=3, K=48->64) then 1x1-style GEMM -> h1h NHWC ----
    im2colT_conv_h<<<dim3(N_HALF / 32, 2), 256>>>(x, colh + COLA, PS_LAT,
        3, 128, 128, 12, 6, 16, 4, 2, 1, 48, 64);
    gemm_imp<<<dim3(2, N_HALF / 128), 256, GEMM_SMEM_H>>>(
        wtsh + OFF_C1, WPLANE, colh + COLA, PS_LAT,
        256, 64, 1, 64, 1, 1, 0, 0, 1, 64, 64, 12, 6,
        0, colh + H1H, PS_H1, 2, nullptr, nullptr, nullptr, 1,
        0, 0, 0, 0, 0, 0);

    // ---- conv2: implicit k4 s2 p1 over h1h -> h2h + h2f, relu ----
    gemm_imp<<<dim3(2, N_LAT / 128), 256, GEMM_SMEM_H>>>(
        wtsh + OFF_C2, WPLANE, colh + H1H, PS_H1,
        256, 4096, 0, 256, 3, 4, -1, -1, 2, 64, 64, 10, 5,
        0, colh + H2H, PS_LAT, 2, h2f, nullptr, nullptr, 1,
        0, 0, 0, 0, 0, 0);

    // ---- residual block helper ----
    auto res = [&](size_t srch, const float* srcf, int offA, int offB,
                   size_t outh, int outPl, float* outf) {
        // 3x3 relu -> tmph
        gemm_imp<<<dim3(2, N_LAT / 128), 256, GEMM_SMEM_H>>>(
            wtsh + offA, WPLANE, colh + srch, PS_LAT,
            256, 2304, 0, 256, 3, 3, -1, -1, 1, 32, 32, 10, 5,
            0, colh + TMPH, PS_LAT, 2, nullptr, nullptr, nullptr, 1,
            0, 0, 0, 0, 0, 0);
        // 1x1 + resid -> out
        gemm_imp<<<dim3(2, N_LAT / 128), 256, GEMM_SMEM_H>>>(
            wtsh + offB, WPLANE, colh + TMPH, PS_LAT,
            256, 256, 0, 256, 3, 1, 0, 0, 1, 32, 32, 10, 5,
            0, colh + outh, PS_LAT, outPl, outf, srcf, nullptr, 0,
            0, 0, 0, 0, 0, 0);
    };
    res(H2H, h2f, OFF_ER1A, OFF_ER1B, ABH, 2, abf);
    res(ABH, abf, OFF_ER2A, OFF_ER2B, ZEH, 3, zef);

    // ---- VQ scores: full-precision GEMM over zeh (3-plane), rowmajor out ----
    // B treated as a 1 x N_LAT "image" (Hin=1, Win=N_LAT) so the loader's
    // pixel decode matches the epilogue's rowmajor decode (logHWo=logWo=15).
    vq_enorm<<<512, 256>>>(embed, enrm);
    gemm_imp<<<dim3(4, N_LAT / 128), 256, GEMM_SMEM_H>>>(
        wtsh + OFF_EMB, WPLANE, colh + ZEH, PS_LAT,
        512, 256, 1, 256, 3, 1, 0, 0, 1, 1, N_LAT, 15, 15,
        1, nullptr, 0, 0, S, nullptr, nullptr, 0,
        1, N_LAT, 1, 1, 0, 0);
    vq_argmin<<<N_LAT / 256, 256>>>(S, enrm, idxp);
    vq_gather<<<4096, 256>>>(zef, embed, idxp, zqf, colh + ZQH, PS_LAT, part);

    // ---- decoder residual blocks ----
    res(ZQH, zqf, OFF_DR1A, OFF_DR1B, ABH, 2, abf);
    res(ABH, abf, OFF_DR2A, OFF_DR2B, BBH, 2, bbf);

    // ---- deconv1: 4 parity implicit GEMMs, NCHW scatter + bias + relu ----
    for (int par = 0; par < 4; par++) {
        int ry = par >> 1, rx = par & 1;
        gemm_imp<<<dim3(2, N_LAT / 128), 256, GEMM_SMEM_H>>>(
            wtsh + OFF_DT1 + par * 262144, WPLANE, colh + BBH, PS_LAT,
            256, 1024, 0, 256, 3, 2, ry - 1, rx - 1, 1, 32, 32, 10, 5,
            1, nullptr, 0, 0, d1, nullptr, dt1_b, 1,
            64, 64, 2, 2, ry, rx);
    }

    // ---- deconv2 + sigmoid ----
    deconv2_sig<<<dim3(4, 32), 256>>>(d1, wpk, dt2_b, out);

    // ---- losses ----
    loss_write<<<1, 256>>>(part, out, out_size);
}